// round 6
// baseline (speedup 1.0000x reference)
#include <cuda_runtime.h>
#include <math.h>
#include <stdint.h>

// ---------------- scratch (no allocations allowed -> __device__ globals) ----
__device__ float g_qkv[200704UL * 1152UL];   // 925 MB
__device__ float g_att[200704UL * 384UL];    // 308 MB

static __device__ __forceinline__ uint32_t s2u(const void* p) {
    return (uint32_t)__cvta_generic_to_shared(p);
}

static __device__ __forceinline__ uint32_t f2tf32(float x) {
    uint32_t t;
    asm("cvt.rna.tf32.f32 %0, %1;" : "=r"(t) : "f"(x));
    return t;
}

static __device__ __forceinline__ void ldsm4(uint32_t r[4], uint32_t addr) {
    asm volatile("ldmatrix.sync.aligned.m8n8.x4.shared.b16 {%0,%1,%2,%3}, [%4];"
                 : "=r"(r[0]), "=r"(r[1]), "=r"(r[2]), "=r"(r[3]) : "r"(addr));
}

static __device__ __forceinline__ void mma_tf32(float c[4], const uint32_t a[4],
                                                uint32_t b0, uint32_t b1) {
    asm volatile(
        "mma.sync.aligned.m16n8k8.row.col.f32.tf32.tf32.f32 "
        "{%0,%1,%2,%3}, {%4,%5,%6,%7}, {%8,%9}, {%0,%1,%2,%3};"
        : "+f"(c[0]), "+f"(c[1]), "+f"(c[2]), "+f"(c[3])
        : "r"(a[0]), "r"(a[1]), "r"(a[2]), "r"(a[3]), "r"(b0), "r"(b1));
}

// ---------------- tf32 tensor-core GEMM:  C = A[M,K] @ W[N,K]^T + bias -------
// 128x128 CTA tile, BK=32, 512 threads = 16 warps (4x4), 32x32 warp tile.
// DOUBLE-BUFFERED smem (one __syncthreads per K-iter); rows padded to 36
// words -> conflict-free LDSM (36 mod 32 = 4).
#define GEMM_SMEM_BYTES (2 * 2 * 128 * 36 * 4)   // 73728

__global__ __launch_bounds__(512) void tf32_gemm_nt(
    const float* __restrict__ A, const float* __restrict__ W,
    const float* __restrict__ bias, float* __restrict__ C,
    int M, int N, int K)
{
    extern __shared__ float sm[];
    float (*As)[128][36] = reinterpret_cast<float(*)[128][36]>(sm);
    float (*Ws)[128][36] = reinterpret_cast<float(*)[128][36]>(sm + 2 * 128 * 36);

    const int tid  = threadIdx.x;
    const int bm   = blockIdx.y * 128;
    const int bn   = blockIdx.x * 128;
    const int lane = tid & 31;
    const int wid  = tid >> 5;
    const int wm   = (wid & 3) * 32;    // warp row offset
    const int wn   = (wid >> 2) * 32;   // warp col offset

    // ldmatrix source coordinates (per-lane)
    const int a_row = wm + (lane & 15);
    const int a_k   = (lane >> 4) << 2;                      // 0 or 4
    const int b_row = wn + (lane & 7) + ((lane & 16) >> 1);  // +8 when lane>=16
    const int b_k   = (lane & 8) >> 1;                       // 0 or 4

    // gmem staging coordinates: 1024 float4 per tile / 512 threads = 2 each
    const int r0 = tid >> 3,         c0 = (tid & 7) << 2;
    const int r1 = (tid + 512) >> 3, c1 = c0;

    float acc[2][4][4];
#pragma unroll
    for (int mt = 0; mt < 2; mt++)
#pragma unroll
        for (int nt = 0; nt < 4; nt++)
#pragma unroll
            for (int i = 0; i < 4; i++) acc[mt][nt][i] = 0.0f;

    const int KT = K >> 5;                // K / 32
    float4 sA0, sA1, sW0, sW1;

    // prologue: stage tile 0 into buffer 0
    sA0 = *(const float4*)(A + (size_t)(bm + r0) * K + c0);
    sA1 = *(const float4*)(A + (size_t)(bm + r1) * K + c1);
    sW0 = *(const float4*)(W + (size_t)(bn + r0) * K + c0);
    sW1 = *(const float4*)(W + (size_t)(bn + r1) * K + c1);
    *(uint4*)&As[0][r0][c0] = make_uint4(f2tf32(sA0.x), f2tf32(sA0.y), f2tf32(sA0.z), f2tf32(sA0.w));
    *(uint4*)&As[0][r1][c1] = make_uint4(f2tf32(sA1.x), f2tf32(sA1.y), f2tf32(sA1.z), f2tf32(sA1.w));
    *(uint4*)&Ws[0][r0][c0] = make_uint4(f2tf32(sW0.x), f2tf32(sW0.y), f2tf32(sW0.z), f2tf32(sW0.w));
    *(uint4*)&Ws[0][r1][c1] = make_uint4(f2tf32(sW1.x), f2tf32(sW1.y), f2tf32(sW1.z), f2tf32(sW1.w));
    __syncthreads();

    for (int it = 0; it < KT; it++) {
        const int cur  = it & 1;
        const int nxt  = cur ^ 1;
        const bool more = (it + 1 < KT);

        // issue next-tile global loads first (latency hidden under the MMAs)
        if (more) {
            const int k0 = (it + 1) << 5;
            sA0 = *(const float4*)(A + (size_t)(bm + r0) * K + k0 + c0);
            sA1 = *(const float4*)(A + (size_t)(bm + r1) * K + k0 + c1);
            sW0 = *(const float4*)(W + (size_t)(bn + r0) * K + k0 + c0);
            sW1 = *(const float4*)(W + (size_t)(bn + r1) * K + k0 + c1);
        }

        // compute on current buffer
#pragma unroll
        for (int s = 0; s < 4; s++) {
            const int k8 = s << 3;
            uint32_t a[2][4], b[2][4];
#pragma unroll
            for (int mt = 0; mt < 2; mt++)
                ldsm4(a[mt], s2u(&As[cur][a_row + mt * 16][k8 + a_k]));
#pragma unroll
            for (int p = 0; p < 2; p++)
                ldsm4(b[p], s2u(&Ws[cur][b_row + p * 16][k8 + b_k]));
#pragma unroll
            for (int mt = 0; mt < 2; mt++)
#pragma unroll
                for (int nt = 0; nt < 4; nt++)
                    mma_tf32(acc[mt][nt], a[mt],
                             b[nt >> 1][(nt & 1) * 2], b[nt >> 1][(nt & 1) * 2 + 1]);
        }

        // fill the other buffer (prev readers of it finished before last sync)
        if (more) {
            *(uint4*)&As[nxt][r0][c0] = make_uint4(f2tf32(sA0.x), f2tf32(sA0.y), f2tf32(sA0.z), f2tf32(sA0.w));
            *(uint4*)&As[nxt][r1][c1] = make_uint4(f2tf32(sA1.x), f2tf32(sA1.y), f2tf32(sA1.z), f2tf32(sA1.w));
            *(uint4*)&Ws[nxt][r0][c0] = make_uint4(f2tf32(sW0.x), f2tf32(sW0.y), f2tf32(sW0.z), f2tf32(sW0.w));
            *(uint4*)&Ws[nxt][r1][c1] = make_uint4(f2tf32(sW1.x), f2tf32(sW1.y), f2tf32(sW1.z), f2tf32(sW1.w));
        }
        __syncthreads();
    }

    // epilogue: c0,c1 -> (row qr, cols qc,qc+1); c2,c3 -> row qr+8
    const int qr = lane >> 2;
    const int qc = (lane & 3) * 2;
#pragma unroll
    for (int mt = 0; mt < 2; mt++) {
        const int row = bm + wm + mt * 16 + qr;
#pragma unroll
        for (int nt = 0; nt < 4; nt++) {
            const int col = bn + wn + nt * 8 + qc;
            const float bx = bias[col], by = bias[col + 1];
            float2 lo = make_float2(acc[mt][nt][0] + bx, acc[mt][nt][1] + by);
            float2 hi = make_float2(acc[mt][nt][2] + bx, acc[mt][nt][3] + by);
            *(float2*)(C + (size_t)row * N + col)       = lo;
            *(float2*)(C + (size_t)(row + 8) * N + col) = hi;
        }
    }
}

// ---------------- windowed attention (shuffle PV, no pbuf smem) ------------
__global__ __launch_bounds__(256) void win_attn(
    const float* __restrict__ qkv, const float* __restrict__ mask,
    const float* __restrict__ rpb, float* __restrict__ out)
{
    __shared__ float qs[49][32];
    __shared__ float kt[32][64];
    __shared__ float vs[49][32];

    const int b = blockIdx.x;
    const int h = blockIdx.y;
    const int tid = threadIdx.x;

    const long base = (long)b * 49 * 1152 + h * 32;

    for (int e = tid; e < 49 * 8; e += 256) {
        int n  = e >> 3;
        int d4 = (e & 7) << 2;
        const float* p = qkv + base + (long)n * 1152 + d4;
        float4 qv = *(const float4*)(p);
        *(float4*)&qs[n][d4] = qv;
        float4 kv = *(const float4*)(p + 384);
        kt[d4 + 0][n] = kv.x; kt[d4 + 1][n] = kv.y;
        kt[d4 + 2][n] = kv.z; kt[d4 + 3][n] = kv.w;
        float4 vv = *(const float4*)(p + 768);
        *(float4*)&vs[n][d4] = vv;
    }
    __syncthreads();

    const int w    = tid >> 5;
    const int lane = tid & 31;
    const float* mrow = mask + (long)(b & 63) * 49 * 49;
    const float scale = 0.17677669529663687f;   // 1/sqrt(32)

    const int j0 = lane, j1 = lane + 32;
    const int rj0 = j0 / 7, cj0 = j0 % 7;
    const int rj1 = j1 / 7, cj1 = j1 % 7;       // only used when j1 < 49

    for (int i = w; i < 49; i += 8) {
        float s0 = 0.0f, s1 = 0.0f;
#pragma unroll
        for (int d = 0; d < 32; d++) {
            float qv = qs[i][d];
            s0 += qv * kt[d][j0];
            s1 += qv * kt[d][j1];
        }
        const int ri = i / 7, ci = i % 7;
        s0 = s0 * scale
           + rpb[((ri - rj0 + 6) * 13 + (ci - cj0 + 6)) * 12 + h]
           + mrow[i * 49 + j0];
        if (j1 < 49) {
            s1 = s1 * scale
               + rpb[((ri - rj1 + 6) * 13 + (ci - cj1 + 6)) * 12 + h]
               + mrow[i * 49 + j1];
        } else {
            s1 = -INFINITY;
        }

        // warp max
        float mx = fmaxf(s0, s1);
#pragma unroll
        for (int off = 16; off > 0; off >>= 1)
            mx = fmaxf(mx, __shfl_xor_sync(0xffffffffu, mx, off));

        float p0 = __expf(s0 - mx);
        float p1 = (j1 < 49) ? __expf(s1 - mx) : 0.0f;
        float sum = p0 + p1;
#pragma unroll
        for (int off = 16; off > 0; off >>= 1)
            sum += __shfl_xor_sync(0xffffffffu, sum, off);
        float inv = 1.0f / sum;
        float q0 = p0 * inv;
        float q1 = p1 * inv;   // zero for lanes with j1 >= 49

        // out[i][lane] = sum_j P[i][j] * v[j][lane]  via register broadcast
        float acc = 0.0f;
#pragma unroll
        for (int j = 0; j < 32; j++)
            acc += __shfl_sync(0xffffffffu, q0, j) * vs[j][lane];
#pragma unroll
        for (int j = 0; j < 17; j++)
            acc += __shfl_sync(0xffffffffu, q1, j) * vs[32 + j][lane];

        out[(long)(b * 49 + i) * 384 + h * 32 + lane] = acc;
    }
}

// ---------------- launch ----------------------------------------------
extern "C" void kernel_launch(void* const* d_in, const int* in_sizes, int n_in,
                              void* d_out, int out_size)
{
    const float* x      = (const float*)d_in[0];
    const float* mask   = (const float*)d_in[1];
    const float* qkv_w  = (const float*)d_in[2];
    const float* qkv_b  = (const float*)d_in[3];
    const float* proj_w = (const float*)d_in[4];
    const float* proj_b = (const float*)d_in[5];
    const float* rpb    = (const float*)d_in[6];
    float* out = (float*)d_out;

    float *qkv, *att;
    cudaGetSymbolAddress((void**)&qkv, g_qkv);
    cudaGetSymbolAddress((void**)&att, g_att);

    cudaFuncSetAttribute(tf32_gemm_nt,
                         cudaFuncAttributeMaxDynamicSharedMemorySize,
                         GEMM_SMEM_BYTES);

    // 1) qkv = x @ qkv_w^T + qkv_b          (M=200704, N=1152, K=384)
    tf32_gemm_nt<<<dim3(1152 / 128, 200704 / 128), 512, GEMM_SMEM_BYTES>>>(
        x, qkv_w, qkv_b, qkv, 200704, 1152, 384);
    // 2) windowed attention -> att (200704 x 384, [b,n,(h,d)] layout)
    win_attn<<<dim3(4096, 12), 256>>>(qkv, mask, rpb, att);

    // 3) out = att @ proj_w^T + proj_b      (M=200704, N=384, K=384)
    tf32_gemm_nt<<<dim3(384 / 128, 200704 / 128), 512, GEMM_SMEM_BYTES>>>(
        att, proj_w, proj_b, out, 200704, 384, 384);
}

// round 10
// speedup vs baseline: 1.1728x; 1.1728x over previous
#include <cuda_runtime.h>
#include <math.h>
#include <stdint.h>

// ---------------- scratch (no allocations allowed -> __device__ globals) ----
__device__ float g_qkv[200704UL * 1152UL];   // 925 MB
__device__ float g_att[200704UL * 384UL];    // 308 MB

static __device__ __forceinline__ uint32_t s2u(const void* p) {
    return (uint32_t)__cvta_generic_to_shared(p);
}

static __device__ __forceinline__ uint32_t f2tf32(float x) {
    uint32_t t;
    asm("cvt.rna.tf32.f32 %0, %1;" : "=r"(t) : "f"(x));
    return t;
}

static __device__ __forceinline__ void ldsm4(uint32_t r[4], uint32_t addr) {
    asm volatile("ldmatrix.sync.aligned.m8n8.x4.shared.b16 {%0,%1,%2,%3}, [%4];"
                 : "=r"(r[0]), "=r"(r[1]), "=r"(r[2]), "=r"(r[3]) : "r"(addr));
}

static __device__ __forceinline__ void mma_tf32(float c[4], const uint32_t a[4],
                                                uint32_t b0, uint32_t b1) {
    asm volatile(
        "mma.sync.aligned.m16n8k8.row.col.f32.tf32.tf32.f32 "
        "{%0,%1,%2,%3}, {%4,%5,%6,%7}, {%8,%9}, {%0,%1,%2,%3};"
        : "+f"(c[0]), "+f"(c[1]), "+f"(c[2]), "+f"(c[3])
        : "r"(a[0]), "r"(a[1]), "r"(a[2]), "r"(a[3]), "r"(b0), "r"(b1));
}

// ---------------- tf32 tensor-core GEMM:  C = A[M,K] @ W[N,K]^T + bias -------
// 128x64 CTA tile, BK=32, 256 threads = 8 warps (4m x 2n), 32x32 warp tile.
// Single-buffered static smem (R5 structure), rows padded to 36 words ->
// conflict-free LDSM. __launch_bounds__(256,3): 3 CTAs/SM = 24 warps.
__global__ __launch_bounds__(256, 3) void tf32_gemm_nt(
    const float* __restrict__ A, const float* __restrict__ W,
    const float* __restrict__ bias, float* __restrict__ C,
    int M, int N, int K)
{
    __shared__ float As[128][36];
    __shared__ float Ws[64][36];

    const int tid  = threadIdx.x;
    const int bm   = blockIdx.y * 128;
    const int bn   = blockIdx.x * 64;
    const int lane = tid & 31;
    const int wid  = tid >> 5;
    const int wm   = (wid & 3) * 32;    // warp row offset (0..96)
    const int wn   = (wid >> 2) * 32;   // warp col offset (0 or 32)

    // ldmatrix source coordinates (per-lane) — identical math to R5
    const int a_row = wm + (lane & 15);
    const int a_k   = (lane >> 4) << 2;                      // 0 or 4
    const int b_row = wn + (lane & 7) + ((lane & 16) >> 1);  // +8 when lane>=16
    const int b_k   = (lane & 8) >> 1;                       // 0 or 4

    // gmem staging: A = 1024 float4 (4/thread), W = 512 float4 (2/thread)
    const int sr = tid >> 3;            // 0..31
    const int sc = (tid & 7) << 2;      // 0,4,...,28

    float acc[2][4][4];
#pragma unroll
    for (int mt = 0; mt < 2; mt++)
#pragma unroll
        for (int nt = 0; nt < 4; nt++)
#pragma unroll
            for (int i = 0; i < 4; i++) acc[mt][nt][i] = 0.0f;

    const int KT = K >> 5;                // K / 32
    float4 sA[4], sW[2];

    // prologue: stage first tile
#pragma unroll
    for (int l = 0; l < 4; l++)
        sA[l] = *(const float4*)(A + (size_t)(bm + sr + l * 32) * K + sc);
#pragma unroll
    for (int l = 0; l < 2; l++)
        sW[l] = *(const float4*)(W + (size_t)(bn + sr + l * 32) * K + sc);

    for (int it = 0; it < KT; it++) {
        // store staged tile (tf32-rounded)
#pragma unroll
        for (int l = 0; l < 4; l++)
            *(uint4*)&As[sr + l * 32][sc] = make_uint4(
                f2tf32(sA[l].x), f2tf32(sA[l].y), f2tf32(sA[l].z), f2tf32(sA[l].w));
#pragma unroll
        for (int l = 0; l < 2; l++)
            *(uint4*)&Ws[sr + l * 32][sc] = make_uint4(
                f2tf32(sW[l].x), f2tf32(sW[l].y), f2tf32(sW[l].z), f2tf32(sW[l].w));
        __syncthreads();

        // prefetch next tile to registers while computing
        if (it + 1 < KT) {
            const int k0 = (it + 1) << 5;
#pragma unroll
            for (int l = 0; l < 4; l++)
                sA[l] = *(const float4*)(A + (size_t)(bm + sr + l * 32) * K + k0 + sc);
#pragma unroll
            for (int l = 0; l < 2; l++)
                sW[l] = *(const float4*)(W + (size_t)(bn + sr + l * 32) * K + k0 + sc);
        }

#pragma unroll
        for (int s = 0; s < 4; s++) {
            const int k8 = s << 3;
            uint32_t a[2][4], b[2][4];
#pragma unroll
            for (int mt = 0; mt < 2; mt++)
                ldsm4(a[mt], s2u(&As[a_row + mt * 16][k8 + a_k]));
#pragma unroll
            for (int p = 0; p < 2; p++)
                ldsm4(b[p], s2u(&Ws[b_row + p * 16][k8 + b_k]));
            // b[p] = { ntile(2p).b0, ntile(2p).b1, ntile(2p+1).b0, ntile(2p+1).b1 }
#pragma unroll
            for (int mt = 0; mt < 2; mt++)
#pragma unroll
                for (int nt = 0; nt < 4; nt++)
                    mma_tf32(acc[mt][nt], a[mt],
                             b[nt >> 1][(nt & 1) * 2], b[nt >> 1][(nt & 1) * 2 + 1]);
        }
        __syncthreads();
    }

    // epilogue: c0,c1 -> (row qr, cols qc,qc+1); c2,c3 -> row qr+8
    const int qr = lane >> 2;
    const int qc = (lane & 3) * 2;
#pragma unroll
    for (int mt = 0; mt < 2; mt++) {
        const int row = bm + wm + mt * 16 + qr;
#pragma unroll
        for (int nt = 0; nt < 4; nt++) {
            const int col = bn + wn + nt * 8 + qc;
            const float bx = bias[col], by = bias[col + 1];
            float2 lo = make_float2(acc[mt][nt][0] + bx, acc[mt][nt][1] + by);
            float2 hi = make_float2(acc[mt][nt][2] + bx, acc[mt][nt][3] + by);
            *(float2*)(C + (size_t)row * N + col)       = lo;
            *(float2*)(C + (size_t)(row + 8) * N + col) = hi;
        }
    }
}

// ---------------- windowed attention (shuffle PV, no pbuf smem) ------------
__global__ __launch_bounds__(256) void win_attn(
    const float* __restrict__ qkv, const float* __restrict__ mask,
    const float* __restrict__ rpb, float* __restrict__ out)
{
    __shared__ float qs[49][32];
    __shared__ float kt[32][64];
    __shared__ float vs[49][32];

    const int b = blockIdx.x;
    const int h = blockIdx.y;
    const int tid = threadIdx.x;

    const long base = (long)b * 49 * 1152 + h * 32;

    for (int e = tid; e < 49 * 8; e += 256) {
        int n  = e >> 3;
        int d4 = (e & 7) << 2;
        const float* p = qkv + base + (long)n * 1152 + d4;
        float4 qv = *(const float4*)(p);
        *(float4*)&qs[n][d4] = qv;
        float4 kv = *(const float4*)(p + 384);
        kt[d4 + 0][n] = kv.x; kt[d4 + 1][n] = kv.y;
        kt[d4 + 2][n] = kv.z; kt[d4 + 3][n] = kv.w;
        float4 vv = *(const float4*)(p + 768);
        *(float4*)&vs[n][d4] = vv;
    }
    __syncthreads();

    const int w    = tid >> 5;
    const int lane = tid & 31;
    const float* mrow = mask + (long)(b & 63) * 49 * 49;
    const float scale = 0.17677669529663687f;   // 1/sqrt(32)

    const int j0 = lane, j1 = lane + 32;
    const int rj0 = j0 / 7, cj0 = j0 % 7;
    const int rj1 = j1 / 7, cj1 = j1 % 7;       // only used when j1 < 49

    for (int i = w; i < 49; i += 8) {
        float s0 = 0.0f, s1 = 0.0f;
#pragma unroll
        for (int d = 0; d < 32; d++) {
            float qv = qs[i][d];
            s0 += qv * kt[d][j0];
            s1 += qv * kt[d][j1];
        }
        const int ri = i / 7, ci = i % 7;
        s0 = s0 * scale
           + rpb[((ri - rj0 + 6) * 13 + (ci - cj0 + 6)) * 12 + h]
           + mrow[i * 49 + j0];
        if (j1 < 49) {
            s1 = s1 * scale
               + rpb[((ri - rj1 + 6) * 13 + (ci - cj1 + 6)) * 12 + h]
               + mrow[i * 49 + j1];
        } else {
            s1 = -INFINITY;
        }

        // warp max
        float mx = fmaxf(s0, s1);
#pragma unroll
        for (int off = 16; off > 0; off >>= 1)
            mx = fmaxf(mx, __shfl_xor_sync(0xffffffffu, mx, off));

        float p0 = __expf(s0 - mx);
        float p1 = (j1 < 49) ? __expf(s1 - mx) : 0.0f;
        float sum = p0 + p1;
#pragma unroll
        for (int off = 16; off > 0; off >>= 1)
            sum += __shfl_xor_sync(0xffffffffu, sum, off);
        float inv = 1.0f / sum;
        float q0 = p0 * inv;
        float q1 = p1 * inv;   // zero for lanes with j1 >= 49

        // out[i][lane] = sum_j P[i][j] * v[j][lane]  via register broadcast
        float acc = 0.0f;
#pragma unroll
        for (int j = 0; j < 32; j++)
            acc += __shfl_sync(0xffffffffu, q0, j) * vs[j][lane];
#pragma unroll
        for (int j = 0; j < 17; j++)
            acc += __shfl_sync(0xffffffffu, q1, j) * vs[32 + j][lane];

        out[(long)(b * 49 + i) * 384 + h * 32 + lane] = acc;
    }
}

// ---------------- launch ----------------------------------------------
extern "C" void kernel_launch(void* const* d_in, const int* in_sizes, int n_in,
                              void* d_out, int out_size)
{
    const float* x      = (const float*)d_in[0];
    const float* mask   = (const float*)d_in[1];
    const float* qkv_w  = (const float*)d_in[2];
    const float* qkv_b  = (const float*)d_in[3];
    const float* proj_w = (const float*)d_in[4];
    const float* proj_b = (const float*)d_in[5];
    const float* rpb    = (const float*)d_in[6];
    float* out = (float*)d_out;

    float *qkv, *att;
    cudaGetSymbolAddress((void**)&qkv, g_qkv);
    cudaGetSymbolAddress((void**)&att, g_att);

    // 1) qkv = x @ qkv_w^T + qkv_b          (M=200704, N=1152, K=384)
    tf32_gemm_nt<<<dim3(1152 / 64, 200704 / 128), 256>>>(x, qkv_w, qkv_b, qkv,
                                                         200704, 1152, 384);
    // 2) windowed attention -> att (200704 x 384, [b,n,(h,d)] layout)
    win_attn<<<dim3(4096, 12), 256>>>(qkv, mask, rpb, att);

    // 3) out = att @ proj_w^T + proj_b      (M=200704, N=384, K=384)
    tf32_gemm_nt<<<dim3(384 / 64, 200704 / 128), 256>>>(att, proj_w, proj_b, out,
                                                        200704, 384, 384);
}

// round 11
// speedup vs baseline: 1.2820x; 1.0931x over previous
#include <cuda_runtime.h>
#include <math.h>
#include <stdint.h>

// ---------------- scratch (no allocations allowed -> __device__ globals) ----
__device__ float g_qkv[200704UL * 1152UL];   // 925 MB
__device__ float g_att[200704UL * 384UL];    // 308 MB

static __device__ __forceinline__ uint32_t s2u(const void* p) {
    return (uint32_t)__cvta_generic_to_shared(p);
}

static __device__ __forceinline__ uint32_t f2tf32(float x) {
    uint32_t t;
    asm("cvt.rna.tf32.f32 %0, %1;" : "=r"(t) : "f"(x));
    return t;
}

static __device__ __forceinline__ void ldsm4(uint32_t r[4], uint32_t addr) {
    asm volatile("ldmatrix.sync.aligned.m8n8.x4.shared.b16 {%0,%1,%2,%3}, [%4];"
                 : "=r"(r[0]), "=r"(r[1]), "=r"(r[2]), "=r"(r[3]) : "r"(addr));
}

static __device__ __forceinline__ void mma_tf32(float c[4], const uint32_t a[4],
                                                uint32_t b0, uint32_t b1) {
    asm volatile(
        "mma.sync.aligned.m16n8k8.row.col.f32.tf32.tf32.f32 "
        "{%0,%1,%2,%3}, {%4,%5,%6,%7}, {%8,%9}, {%0,%1,%2,%3};"
        : "+f"(c[0]), "+f"(c[1]), "+f"(c[2]), "+f"(c[3])
        : "r"(a[0]), "r"(a[1]), "r"(a[2]), "r"(a[3]), "r"(b0), "r"(b1));
}

// ---------------- tf32 tensor-core GEMM:  C = A[M,K] @ W[N,K]^T + bias -------
// 128x128 CTA tile, BK=32, 256 threads = 8 warps (2m x 4n), 64x32 warp tile.
// MMA/LDSM ratio 2.67 (was 2.0 at 32x32) -> 25% less smem read traffic.
// Single-buffered smem, rows padded to 36 words (conflict-free LDSM).
// __launch_bounds__(256,2): <=128 regs, 2 CTAs/SM.
__global__ __launch_bounds__(256, 2) void tf32_gemm_nt(
    const float* __restrict__ A, const float* __restrict__ W,
    const float* __restrict__ bias, float* __restrict__ C,
    int M, int N, int K)
{
    __shared__ float As[128][36];
    __shared__ float Ws[128][36];

    const int tid  = threadIdx.x;
    const int bm   = blockIdx.y * 128;
    const int bn   = blockIdx.x * 128;
    const int lane = tid & 31;
    const int wid  = tid >> 5;
    const int wm   = (wid & 1) * 64;    // warp row offset (0 or 64)
    const int wn   = (wid >> 1) * 32;   // warp col offset (0,32,64,96)

    // ldmatrix source coordinates (per-lane) — same lane math as validated R5
    const int a_row = wm + (lane & 15);
    const int a_k   = (lane >> 4) << 2;                      // 0 or 4
    const int b_row = wn + (lane & 7) + ((lane & 16) >> 1);  // +8 when lane>=16
    const int b_k   = (lane & 8) >> 1;                       // 0 or 4

    // gmem staging: A and W each 1024 float4 over 256 threads = 4 each
    const int sr = tid >> 3;            // 0..31
    const int sc = (tid & 7) << 2;      // 0,4,...,28

    float acc[4][4][4];
#pragma unroll
    for (int mt = 0; mt < 4; mt++)
#pragma unroll
        for (int nt = 0; nt < 4; nt++)
#pragma unroll
            for (int i = 0; i < 4; i++) acc[mt][nt][i] = 0.0f;

    const int KT = K >> 5;                // K / 32
    float4 sA[4], sW[4];

    // prologue: stage first tile
#pragma unroll
    for (int l = 0; l < 4; l++) {
        sA[l] = *(const float4*)(A + (size_t)(bm + sr + l * 32) * K + sc);
        sW[l] = *(const float4*)(W + (size_t)(bn + sr + l * 32) * K + sc);
    }

    for (int it = 0; it < KT; it++) {
        // store staged tile (tf32-rounded)
#pragma unroll
        for (int l = 0; l < 4; l++) {
            *(uint4*)&As[sr + l * 32][sc] = make_uint4(
                f2tf32(sA[l].x), f2tf32(sA[l].y), f2tf32(sA[l].z), f2tf32(sA[l].w));
            *(uint4*)&Ws[sr + l * 32][sc] = make_uint4(
                f2tf32(sW[l].x), f2tf32(sW[l].y), f2tf32(sW[l].z), f2tf32(sW[l].w));
        }
        __syncthreads();

        // prefetch next tile to registers while computing
        if (it + 1 < KT) {
            const int k0 = (it + 1) << 5;
#pragma unroll
            for (int l = 0; l < 4; l++) {
                sA[l] = *(const float4*)(A + (size_t)(bm + sr + l * 32) * K + k0 + sc);
                sW[l] = *(const float4*)(W + (size_t)(bn + sr + l * 32) * K + k0 + sc);
            }
        }

#pragma unroll
        for (int s = 0; s < 4; s++) {
            const int k8 = s << 3;
            uint32_t a[4][4], b[2][4];
#pragma unroll
            for (int mt = 0; mt < 4; mt++)
                ldsm4(a[mt], s2u(&As[a_row + mt * 16][k8 + a_k]));
#pragma unroll
            for (int p = 0; p < 2; p++)
                ldsm4(b[p], s2u(&Ws[b_row + p * 16][k8 + b_k]));
            // b[p] = { ntile(2p).b0, ntile(2p).b1, ntile(2p+1).b0, ntile(2p+1).b1 }
#pragma unroll
            for (int mt = 0; mt < 4; mt++)
#pragma unroll
                for (int nt = 0; nt < 4; nt++)
                    mma_tf32(acc[mt][nt], a[mt],
                             b[nt >> 1][(nt & 1) * 2], b[nt >> 1][(nt & 1) * 2 + 1]);
        }
        __syncthreads();
    }

    // epilogue: c0,c1 -> (row qr, cols qc,qc+1); c2,c3 -> row qr+8
    const int qr = lane >> 2;
    const int qc = (lane & 3) * 2;
#pragma unroll
    for (int mt = 0; mt < 4; mt++) {
        const int row = bm + wm + mt * 16 + qr;
#pragma unroll
        for (int nt = 0; nt < 4; nt++) {
            const int col = bn + wn + nt * 8 + qc;
            const float bx = bias[col], by = bias[col + 1];
            float2 lo = make_float2(acc[mt][nt][0] + bx, acc[mt][nt][1] + by);
            float2 hi = make_float2(acc[mt][nt][2] + bx, acc[mt][nt][3] + by);
            *(float2*)(C + (size_t)row * N + col)       = lo;
            *(float2*)(C + (size_t)(row + 8) * N + col) = hi;
        }
    }
}

// ---------------- windowed attention (shuffle PV, no pbuf smem) ------------
__global__ __launch_bounds__(256) void win_attn(
    const float* __restrict__ qkv, const float* __restrict__ mask,
    const float* __restrict__ rpb, float* __restrict__ out)
{
    __shared__ float qs[49][32];
    __shared__ float kt[32][64];
    __shared__ float vs[49][32];

    const int b = blockIdx.x;
    const int h = blockIdx.y;
    const int tid = threadIdx.x;

    const long base = (long)b * 49 * 1152 + h * 32;

    for (int e = tid; e < 49 * 8; e += 256) {
        int n  = e >> 3;
        int d4 = (e & 7) << 2;
        const float* p = qkv + base + (long)n * 1152 + d4;
        float4 qv = *(const float4*)(p);
        *(float4*)&qs[n][d4] = qv;
        float4 kv = *(const float4*)(p + 384);
        kt[d4 + 0][n] = kv.x; kt[d4 + 1][n] = kv.y;
        kt[d4 + 2][n] = kv.z; kt[d4 + 3][n] = kv.w;
        float4 vv = *(const float4*)(p + 768);
        *(float4*)&vs[n][d4] = vv;
    }
    __syncthreads();

    const int w    = tid >> 5;
    const int lane = tid & 31;
    const float* mrow = mask + (long)(b & 63) * 49 * 49;
    const float scale = 0.17677669529663687f;   // 1/sqrt(32)

    const int j0 = lane, j1 = lane + 32;
    const int rj0 = j0 / 7, cj0 = j0 % 7;
    const int rj1 = j1 / 7, cj1 = j1 % 7;       // only used when j1 < 49

    for (int i = w; i < 49; i += 8) {
        float s0 = 0.0f, s1 = 0.0f;
#pragma unroll
        for (int d = 0; d < 32; d++) {
            float qv = qs[i][d];
            s0 += qv * kt[d][j0];
            s1 += qv * kt[d][j1];
        }
        const int ri = i / 7, ci = i % 7;
        s0 = s0 * scale
           + rpb[((ri - rj0 + 6) * 13 + (ci - cj0 + 6)) * 12 + h]
           + mrow[i * 49 + j0];
        if (j1 < 49) {
            s1 = s1 * scale
               + rpb[((ri - rj1 + 6) * 13 + (ci - cj1 + 6)) * 12 + h]
               + mrow[i * 49 + j1];
        } else {
            s1 = -INFINITY;
        }

        // warp max
        float mx = fmaxf(s0, s1);
#pragma unroll
        for (int off = 16; off > 0; off >>= 1)
            mx = fmaxf(mx, __shfl_xor_sync(0xffffffffu, mx, off));

        float p0 = __expf(s0 - mx);
        float p1 = (j1 < 49) ? __expf(s1 - mx) : 0.0f;
        float sum = p0 + p1;
#pragma unroll
        for (int off = 16; off > 0; off >>= 1)
            sum += __shfl_xor_sync(0xffffffffu, sum, off);
        float inv = 1.0f / sum;
        float q0 = p0 * inv;
        float q1 = p1 * inv;   // zero for lanes with j1 >= 49

        // out[i][lane] = sum_j P[i][j] * v[j][lane]  via register broadcast
        float acc = 0.0f;
#pragma unroll
        for (int j = 0; j < 32; j++)
            acc += __shfl_sync(0xffffffffu, q0, j) * vs[j][lane];
#pragma unroll
        for (int j = 0; j < 17; j++)
            acc += __shfl_sync(0xffffffffu, q1, j) * vs[32 + j][lane];

        out[(long)(b * 49 + i) * 384 + h * 32 + lane] = acc;
    }
}

// ---------------- launch ----------------------------------------------
extern "C" void kernel_launch(void* const* d_in, const int* in_sizes, int n_in,
                              void* d_out, int out_size)
{
    const float* x      = (const float*)d_in[0];
    const float* mask   = (const float*)d_in[1];
    const float* qkv_w  = (const float*)d_in[2];
    const float* qkv_b  = (const float*)d_in[3];
    const float* proj_w = (const float*)d_in[4];
    const float* proj_b = (const float*)d_in[5];
    const float* rpb    = (const float*)d_in[6];
    float* out = (float*)d_out;

    float *qkv, *att;
    cudaGetSymbolAddress((void**)&qkv, g_qkv);
    cudaGetSymbolAddress((void**)&att, g_att);

    // 1) qkv = x @ qkv_w^T + qkv_b          (M=200704, N=1152, K=384)
    tf32_gemm_nt<<<dim3(1152 / 128, 200704 / 128), 256>>>(x, qkv_w, qkv_b, qkv,
                                                          200704, 1152, 384);
    // 2) windowed attention -> att (200704 x 384, [b,n,(h,d)] layout)
    win_attn<<<dim3(4096, 12), 256>>>(qkv, mask, rpb, att);

    // 3) out = att @ proj_w^T + proj_b      (M=200704, N=384, K=384)
    tf32_gemm_nt<<<dim3(384 / 128, 200704 / 128), 256>>>(att, proj_w, proj_b, out,
                                                         200704, 384, 384);
}